// round 4
// baseline (speedup 1.0000x reference)
#include <cuda_runtime.h>
#include <cuda_bf16.h>
#include <math.h>
#include <stdint.h>

// ---------------- problem constants ----------------
#define VV    50000
#define OOV_N 100
#define VO    50100
#define EE    128
#define HH    256
#define BB    32
#define SS    256
#define TT    16
#define BTVO  ((size_t)BB * TT * VO)   // 25,651,200
#define LOG1EM10 (-23.025850929940457f)

// ---------------- static device scratch (no runtime alloc) ----------------
__device__ float d_xe_enc[BB * SS * EE];
__device__ float d_xe_dec[BB * TT * EE];
__device__ float d_zx_enc[(size_t)BB * SS * 4 * HH];
__device__ float d_zx_dec[BB * TT * 4 * HH];
__device__ float d_enc_out[(size_t)BB * SS * HH];
__device__ float d_dec_out[BB * TT * HH];
__device__ float d_ehec[2 * BB * HH];      // rows 0..31 = eh, 32..63 = ec
__device__ float d_h0c0[2 * BB * HH];      // rows 0..31 = h0, 32..63 = c0
__device__ float d_dWa[BB * TT * HH];
__device__ float d_encWc[(size_t)BB * SS * HH];
__device__ float d_cat[BB * TT * 2 * HH];
__device__ float d_attn[BB * TT * HH];
__device__ float d_rowsum[BB * TT];
__device__ float d_logz[BB * TT];
__device__ float d_fixval[BB * TT * SS];
__device__ float d_copyacc[BTVO];          // dense copy accumulation (~103 MB)
__device__ float d_zero[BB * HH];          // stays zero forever

// grid-barrier state (self-resetting, safe across graph replays)
__device__ volatile unsigned g_bar_cnt;
__device__ volatile unsigned g_bar_gen;

// ================= grid barrier (all CTAs co-resident) =================
__device__ __forceinline__ void grid_barrier(unsigned nblocks) {
    __threadfence();
    __syncthreads();
    if (threadIdx.x == 0) {
        unsigned gen = g_bar_gen;
        unsigned arr = atomicAdd((unsigned*)&g_bar_cnt, 1u);
        if (arr == nblocks - 1u) {
            g_bar_cnt = 0u;
            __threadfence();
            g_bar_gen = gen + 1u;
        } else {
            while (g_bar_gen == gen) { }
        }
        __threadfence();
    }
    __syncthreads();
}

// ================= embedding gather (enc + dec) =================
__global__ void embed_kernel(const int* __restrict__ x, const int* __restrict__ dx,
                             const float* __restrict__ emb) {
    const int BSE = BB * SS * EE;
    const int BTE = BB * TT * EE;
    int g = blockIdx.x * blockDim.x + threadIdx.x;
    if (g < BSE) {
        int tok = x[g / EE];
        d_xe_enc[g] = emb[(size_t)tok * EE + (g % EE)];
    } else if (g < BSE + BTE) {
        int g2 = g - BSE;
        int tok = dx[g2 / EE];
        d_xe_dec[g2] = emb[(size_t)tok * EE + (g2 % EE)];
    }
}

// ================= generic SGEMM: C = op(A @ B + bias) =================
// A: MxK row-major, B: KxN row-major, C: MxN with row stride ldc.
// MODE 0: none, 1: tanh, 3: store raw logits + accumulate per-row exp-sums
// into Rsum via __expf (vocab GEMM). K must be a multiple of 16.
template <int MODE>
__global__ void __launch_bounds__(256, 2)
sgemm_kernel(const float* __restrict__ A, const float* __restrict__ B,
             float* __restrict__ C, int M, int N, int K, int ldc,
             const float* __restrict__ bias, float* __restrict__ Rsum) {
    __shared__ float As[16][132];
    __shared__ float Bs[16][132];
    __shared__ float rsum[128];

    const int tid  = threadIdx.x;
    const int row0 = blockIdx.y * 128;
    const int col0 = blockIdx.x * 128;
    const int rowb = (tid >> 4) * 8;
    const int colb = (tid & 15) * 8;

    if (MODE == 3 && tid < 128) rsum[tid] = 0.f;

    float acc[8][8];
#pragma unroll
    for (int i = 0; i < 8; i++)
#pragma unroll
        for (int j = 0; j < 8; j++) acc[i][j] = 0.f;

    const int am  = tid >> 1;          // 0..127
    const int akq = (tid & 1) * 4;     // 0 or 4
    const int bkk = tid >> 5;          // 0..7
    const int bn4 = (tid & 31) * 4;    // 0..124

    for (int k0 = 0; k0 < K; k0 += 16) {
        // A tile -> As[k][m] (transposed), two float4 per thread (k halves)
        {
            int r = row0 + am;
            float4 a0 = make_float4(0.f, 0.f, 0.f, 0.f);
            float4 a1 = make_float4(0.f, 0.f, 0.f, 0.f);
            if (r < M) {
                const float* ar = &A[(size_t)r * K + k0];
                a0 = *reinterpret_cast<const float4*>(&ar[akq]);
                a1 = *reinterpret_cast<const float4*>(&ar[akq + 8]);
            }
            As[akq + 0][am] = a0.x; As[akq + 1][am] = a0.y;
            As[akq + 2][am] = a0.z; As[akq + 3][am] = a0.w;
            As[akq + 8][am] = a1.x; As[akq + 9][am] = a1.y;
            As[akq + 10][am] = a1.z; As[akq + 11][am] = a1.w;
        }
        // B tile -> Bs[k][n], two rows per thread
        {
            int c = col0 + bn4;
#pragma unroll
            for (int h = 0; h < 2; h++) {
                const float* brow = &B[(size_t)(k0 + bkk + h * 8) * N];
                if (c + 3 < N) {
                    *reinterpret_cast<float4*>(&Bs[bkk + h * 8][bn4]) =
                        *reinterpret_cast<const float4*>(&brow[c]);
                } else {
#pragma unroll
                    for (int j = 0; j < 4; j++)
                        Bs[bkk + h * 8][bn4 + j] = (c + j < N) ? brow[c + j] : 0.f;
                }
            }
        }
        __syncthreads();

#pragma unroll
        for (int kk = 0; kk < 16; kk++) {
            float a[8], b[8];
            float4 a0 = *reinterpret_cast<const float4*>(&As[kk][rowb]);
            float4 a1 = *reinterpret_cast<const float4*>(&As[kk][rowb + 4]);
            float4 b0 = *reinterpret_cast<const float4*>(&Bs[kk][colb]);
            float4 b1 = *reinterpret_cast<const float4*>(&Bs[kk][colb + 4]);
            a[0]=a0.x; a[1]=a0.y; a[2]=a0.z; a[3]=a0.w;
            a[4]=a1.x; a[5]=a1.y; a[6]=a1.z; a[7]=a1.w;
            b[0]=b0.x; b[1]=b0.y; b[2]=b0.z; b[3]=b0.w;
            b[4]=b1.x; b[5]=b1.y; b[6]=b1.z; b[7]=b1.w;
#pragma unroll
            for (int i = 0; i < 8; i++)
#pragma unroll
                for (int j = 0; j < 8; j++) acc[i][j] += a[i] * b[j];
        }
        __syncthreads();
    }

#pragma unroll
    for (int i = 0; i < 8; i++) {
        int r = row0 + rowb + i;
        if (r >= M) break;
        float part = 0.f;
#pragma unroll
        for (int j = 0; j < 8; j++) {
            int c = col0 + colb + j;
            if (c < N) {
                float v = acc[i][j];
                if (bias) v += bias[c];
                if (MODE == 1) v = tanhf(v);
                C[(size_t)r * ldc + c] = v;
                if (MODE == 3) part += __expf(v);
            }
        }
        if (MODE == 3) atomicAdd(&rsum[rowb + i], part);
    }
    if (MODE == 3) {
        __syncthreads();
        if (tid < 128 && row0 + tid < M && rsum[tid] != 0.f)
            atomicAdd(&Rsum[row0 + tid], rsum[tid]);
    }
}

// ================= persistent LSTM =================
// 64 CTAs x 256 threads. CTA owns 4 hidden units (all 4 gates, all 32 batches).
__global__ void __launch_bounds__(256, 1)
lstm_kernel(const float* __restrict__ zx, const float* __restrict__ U,
            const float* __restrict__ h0, const float* __restrict__ c0,
            float* __restrict__ hist, float* __restrict__ h_fin,
            float* __restrict__ c_fin, int steps) {
    __shared__ float hs[256 * 33];   // [k][b] padded
    __shared__ float zs[4 * 128];    // [gate][u*32+b]

    const int tid = threadIdx.x;
    const int u0  = blockIdx.x * 4;

    const int bl = tid & 15;
    const int gg = (tid >> 4) & 3;
    const int uu_g = tid >> 6;
    const int j  = gg * 256 + u0 + uu_g;
    const int b1 = bl, b2 = bl + 16;

    const int ub = tid & 31;
    const int uu = tid >> 5;
    float c_reg = 0.f;
    if (tid < 128) c_reg = c0 ? c0[ub * 256 + u0 + uu] : 0.f;

    const unsigned nblk = gridDim.x;

    for (int s = 0; s < steps; s++) {
        if (s == 0) {
            for (int b = 0; b < 32; b++)
                hs[tid * 33 + b] = h0[b * 256 + tid];
        } else {
            for (int b = 0; b < 32; b++)
                hs[tid * 33 + b] = hist[((size_t)b * steps + (s - 1)) * 256 + tid];
        }
        __syncthreads();

        float a1 = zx[((size_t)b1 * steps + s) * 1024 + j];
        float a2 = zx[((size_t)b2 * steps + s) * 1024 + j];
#pragma unroll 8
        for (int k = 0; k < 256; k++) {
            float uk = U[k * 1024 + j];
            a1 += uk * hs[k * 33 + b1];
            a2 += uk * hs[k * 33 + b2];
        }
        zs[gg * 128 + uu_g * 32 + b1] = a1;
        zs[gg * 128 + uu_g * 32 + b2] = a2;
        __syncthreads();

        if (tid < 128) {
            float iv = zs[0 * 128 + uu * 32 + ub];
            float fv = zs[1 * 128 + uu * 32 + ub];
            float gv = zs[2 * 128 + uu * 32 + ub];
            float ov = zs[3 * 128 + uu * 32 + ub];
            float ig = 1.f / (1.f + expf(-iv));
            float fg = 1.f / (1.f + expf(-fv));
            float og = 1.f / (1.f + expf(-ov));
            c_reg = fg * c_reg + ig * tanhf(gv);
            float h = og * tanhf(c_reg);
            hist[((size_t)ub * steps + s) * 256 + u0 + uu] = h;
            if (s == steps - 1) {
                h_fin[ub * 256 + u0 + uu] = h;
                c_fin[ub * 256 + u0 + uu] = c_reg;
            }
        }
        grid_barrier(nblk);
    }
}

// ================= fused attention per (b,t) =================
__global__ void __launch_bounds__(256)
attn_kernel(const float* __restrict__ dWa, const float* __restrict__ enc,
            const float* __restrict__ dec, const int* __restrict__ x_len,
            float* __restrict__ cat) {
    __shared__ float q[256];
    __shared__ float aw[256];
    __shared__ float red[8];

    const int bt = blockIdx.x;
    const int b  = bt / TT;
    const int tid = threadIdx.x;

    q[tid] = dWa[(size_t)bt * 256 + tid];
    __syncthreads();

    const float* er = enc + ((size_t)b * SS + tid) * 256;
    float dot = 0.f;
#pragma unroll 4
    for (int k = 0; k < 256; k += 4) {
        float4 e = *reinterpret_cast<const float4*>(&er[k]);
        dot += q[k] * e.x + q[k + 1] * e.y + q[k + 2] * e.z + q[k + 3] * e.w;
    }
    const int len = x_len[b];
    float sc = (tid < len) ? dot : -1e30f;

    float m = sc;
#pragma unroll
    for (int o = 16; o; o >>= 1) m = fmaxf(m, __shfl_xor_sync(~0u, m, o));
    if ((tid & 31) == 0) red[tid >> 5] = m;
    __syncthreads();
    float mx = red[0];
#pragma unroll
    for (int w = 1; w < 8; w++) mx = fmaxf(mx, red[w]);
    __syncthreads();

    float e = (tid < len) ? __expf(sc - mx) : 0.f;
    float sm = e;
#pragma unroll
    for (int o = 16; o; o >>= 1) sm += __shfl_xor_sync(~0u, sm, o);
    if ((tid & 31) == 0) red[tid >> 5] = sm;
    __syncthreads();
    float tot = 0.f;
#pragma unroll
    for (int w = 0; w < 8; w++) tot += red[w];
    aw[tid] = e / tot;
    __syncthreads();

    float cx = 0.f;
    const float* eb = enc + (size_t)b * SS * 256 + tid;
    for (int s = 0; s < SS; s++) cx += aw[s] * eb[(size_t)s * 256];

    cat[(size_t)bt * 512 + tid]       = cx;
    cat[(size_t)bt * 512 + 256 + tid] = dec[(size_t)bt * 256 + tid];
}

// ================= rowsum init (pad contribution: 100 * 1e-10) =================
__global__ void rowsum_init_kernel(float* __restrict__ rs) {
    int i = threadIdx.x + blockIdx.x * blockDim.x;
    if (i < BB * TT) rs[i] = 1e-8f;
}

// ================= zero exactly the copy-scatter targets =================
__global__ void copyzero_kernel(float* __restrict__ copyacc, const int* __restrict__ xov,
                                const int* __restrict__ x_len) {
    const int bt = blockIdx.x;
    const int b  = bt / TT;
    const int s  = threadIdx.x;
    if (s < x_len[b]) copyacc[(size_t)bt * VO + xov[b * SS + s]] = 0.f;
}

// ================= copy scores + scatter into copyacc, add to rowsum =================
__global__ void __launch_bounds__(256)
copy_scatter_kernel(const float* __restrict__ encWc, const float* __restrict__ attn,
                    const int* __restrict__ xov, const int* __restrict__ x_len,
                    float* __restrict__ copyacc, float* __restrict__ rowsum) {
    __shared__ float a[256];
    const int bt = blockIdx.x;
    const int b  = bt / TT;
    const int tid = threadIdx.x;

    a[tid] = attn[(size_t)bt * 256 + tid];
    __syncthreads();

    if (tid < x_len[b]) {
        const float* r = encWc + ((size_t)b * SS + tid) * 256;
        float dot = 0.f;
#pragma unroll 4
        for (int k = 0; k < 256; k += 4) {
            float4 e = *reinterpret_cast<const float4*>(&r[k]);
            dot += a[k] * e.x + a[k + 1] * e.y + a[k + 2] * e.z + a[k + 3] * e.w;
        }
        float v = expf(dot);
        atomicAdd(&copyacc[(size_t)bt * VO + xov[b * SS + tid]], v);
        atomicAdd(&rowsum[bt], v);
    }
}

// ================= T1: compute fixed values for touched entries =================
// fixval[bt][s] = log(exp(logit) + copyacc)   (races-free: reads only)
__global__ void fixval_kernel(const float* __restrict__ out, const float* __restrict__ copyacc,
                              const int* __restrict__ xov, const int* __restrict__ x_len,
                              float* __restrict__ fixval) {
    const int bt = blockIdx.x;
    const int b  = bt / TT;
    const int s  = threadIdx.x;
    if (s < x_len[b]) {
        int idx = xov[b * SS + s];
        float base = (idx < VV) ? expf(out[(size_t)bt * VO + idx]) : 1e-10f;
        fixval[bt * SS + s] = logf(base + copyacc[(size_t)bt * VO + idx]);
    }
}

// ================= logZ per row =================
__global__ void logz_kernel(const float* __restrict__ rs, float* __restrict__ lz) {
    int i = threadIdx.x + blockIdx.x * blockDim.x;
    if (i < BB * TT) lz[i] = logf(rs[i]);
}

// ================= normalize: out = logit - logZ (OOV -> const) =================
__global__ void finalize_kernel(float* __restrict__ out, const float* __restrict__ lz) {
    const int row = blockIdx.y;
    const int c4  = (blockIdx.x * 256 + threadIdx.x) * 4;
    if (c4 >= VO) return;
    float z = lz[row];
    float* p = out + (size_t)row * VO + c4;
    if (c4 + 3 < VV) {
        float4 v = *reinterpret_cast<float4*>(p);
        v.x -= z; v.y -= z; v.z -= z; v.w -= z;
        *reinterpret_cast<float4*>(p) = v;
    } else {
#pragma unroll
        for (int j = 0; j < 4; j++) {
            int c = c4 + j;
            if (c < VO) p[j] = (c < VV) ? p[j] - z : LOG1EM10 - z;
        }
    }
}

// ================= T2: write fixed values (idempotent for duplicates) =================
__global__ void fixwrite_kernel(float* __restrict__ out, const float* __restrict__ fixval,
                                const float* __restrict__ lz, const int* __restrict__ xov,
                                const int* __restrict__ x_len) {
    const int bt = blockIdx.x;
    const int b  = bt / TT;
    const int s  = threadIdx.x;
    if (s < x_len[b]) {
        int idx = xov[b * SS + s];
        out[(size_t)bt * VO + idx] = fixval[bt * SS + s] - lz[bt];
    }
}

// ================= host side =================
static void run_gemm(const float* A, const float* B, float* C, int M, int N, int K,
                     int ldc, const float* bias, int mode, float* rsum) {
    dim3 grid((N + 127) / 128, (M + 127) / 128);
    if (mode == 0)      sgemm_kernel<0><<<grid, 256>>>(A, B, C, M, N, K, ldc, bias, rsum);
    else if (mode == 1) sgemm_kernel<1><<<grid, 256>>>(A, B, C, M, N, K, ldc, bias, rsum);
    else                sgemm_kernel<3><<<grid, 256>>>(A, B, C, M, N, K, ldc, bias, rsum);
}

extern "C" void kernel_launch(void* const* d_in, const int* in_sizes, int n_in,
                              void* d_out, int out_size) {
    const int*   x     = (const int*)d_in[0];
    const int*   xov   = (const int*)d_in[1];
    const int*   xlen  = (const int*)d_in[2];
    const int*   dx    = (const int*)d_in[3];
    const float* emb   = (const float*)d_in[4];
    const float* Wenc  = (const float*)d_in[5];
    const float* Uenc  = (const float*)d_in[6];
    const float* benc  = (const float*)d_in[7];
    const float* We2d  = (const float*)d_in[8];
    const float* be2d  = (const float*)d_in[9];
    const float* Wdec  = (const float*)d_in[10];
    const float* Udec  = (const float*)d_in[11];
    const float* bdec  = (const float*)d_in[12];
    const float* Wattn = (const float*)d_in[13];
    const float* Wout  = (const float*)d_in[14];
    const float* bout  = (const float*)d_in[15];
    const float* Wgen  = (const float*)d_in[16];
    const float* Wcopy = (const float*)d_in[17];
    const float* bcopy = (const float*)d_in[18];
    float* out = (float*)d_out;
    (void)in_sizes; (void)n_in; (void)out_size;

    void* p;
    cudaGetSymbolAddress(&p, d_xe_enc);  float* s_xe_enc  = (float*)p;
    cudaGetSymbolAddress(&p, d_xe_dec);  float* s_xe_dec  = (float*)p;
    cudaGetSymbolAddress(&p, d_zx_enc);  float* s_zx_enc  = (float*)p;
    cudaGetSymbolAddress(&p, d_zx_dec);  float* s_zx_dec  = (float*)p;
    cudaGetSymbolAddress(&p, d_enc_out); float* s_enc_out = (float*)p;
    cudaGetSymbolAddress(&p, d_dec_out); float* s_dec_out = (float*)p;
    cudaGetSymbolAddress(&p, d_ehec);    float* s_ehec    = (float*)p;
    cudaGetSymbolAddress(&p, d_h0c0);    float* s_h0c0    = (float*)p;
    cudaGetSymbolAddress(&p, d_dWa);     float* s_dWa     = (float*)p;
    cudaGetSymbolAddress(&p, d_encWc);   float* s_encWc   = (float*)p;
    cudaGetSymbolAddress(&p, d_cat);     float* s_cat     = (float*)p;
    cudaGetSymbolAddress(&p, d_attn);    float* s_attn    = (float*)p;
    cudaGetSymbolAddress(&p, d_rowsum);  float* s_rowsum  = (float*)p;
    cudaGetSymbolAddress(&p, d_logz);    float* s_logz    = (float*)p;
    cudaGetSymbolAddress(&p, d_fixval);  float* s_fixval  = (float*)p;
    cudaGetSymbolAddress(&p, d_copyacc); float* s_copyacc = (float*)p;
    cudaGetSymbolAddress(&p, d_zero);    float* s_zero    = (float*)p;

    // 1. embeddings
    {
        int total = BB * SS * EE + BB * TT * EE;
        embed_kernel<<<(total + 255) / 256, 256>>>(x, dx, emb);
    }
    // 2/3. zx precompute (x@W + b)
    run_gemm(s_xe_enc, Wenc, s_zx_enc, BB * SS, 4 * HH, EE, 4 * HH, benc, 0, nullptr);
    run_gemm(s_xe_dec, Wdec, s_zx_dec, BB * TT, 4 * HH, EE, 4 * HH, bdec, 0, nullptr);
    // 4. encoder LSTM
    lstm_kernel<<<64, 256>>>(s_zx_enc, Uenc, s_zero, nullptr,
                             s_enc_out, s_ehec, s_ehec + BB * HH, SS);
    // 5. h0/c0 = [eh;ec] @ We2d + be2d
    run_gemm(s_ehec, We2d, s_h0c0, 2 * BB, HH, HH, HH, be2d, 0, nullptr);
    // 6. decoder LSTM (final h,c straight into output tail)
    lstm_kernel<<<64, 256>>>(s_zx_dec, Udec, s_h0c0, s_h0c0 + BB * HH,
                             s_dec_out, out + BTVO, out + BTVO + BB * HH, TT);
    // 7. dWa = dec_out @ Wattn
    run_gemm(s_dec_out, Wattn, s_dWa, BB * TT, HH, HH, HH, nullptr, 0, nullptr);
    // 8. encWc = tanh(enc_out @ Wcopy + bcopy)
    run_gemm(s_enc_out, Wcopy, s_encWc, BB * SS, HH, HH, HH, bcopy, 1, nullptr);
    // 9. attention -> cat
    attn_kernel<<<BB * TT, 256>>>(s_dWa, s_enc_out, s_dec_out, xlen, s_cat);
    // 10. attn_out = tanh(cat @ Wout + bout)
    run_gemm(s_cat, Wout, s_attn, BB * TT, HH, 2 * HH, HH, bout, 1, nullptr);
    // 11. rowsum init (OOV pad contribution 100*1e-10)
    rowsum_init_kernel<<<2, 256>>>(s_rowsum);
    // 12. logits = attn_out @ Wgen into out (row stride VO) + fused exp-rowsums
    run_gemm(s_attn, Wgen, out, BB * TT, VV, HH, VO, nullptr, 3, s_rowsum);
    // 13. zero the scatter targets, then scatter copy scores
    copyzero_kernel<<<BB * TT, 256>>>(s_copyacc, xov, xlen);
    copy_scatter_kernel<<<BB * TT, 256>>>(s_encWc, s_attn, xov, xlen, s_copyacc, s_rowsum);
    // 14. fixval = log(exp(logit) + copy) for touched entries (race-free staging)
    fixval_kernel<<<BB * TT, 256>>>(out, s_copyacc, xov, xlen, s_fixval);
    // 15. logZ
    logz_kernel<<<2, 256>>>(s_rowsum, s_logz);
    // 16. normalize whole tensor: logit - logZ  (OOV -> log(1e-10) - logZ)
    {
        dim3 grid((VO + 1023) / 1024, BB * TT);
        finalize_kernel<<<grid, 256>>>(out, s_logz);
    }
    // 17. overwrite touched entries with fixed values
    fixwrite_kernel<<<BB * TT, 256>>>(out, s_fixval, s_logz, xov, xlen);
}

// round 5
// speedup vs baseline: 1.4027x; 1.4027x over previous
#include <cuda_runtime.h>
#include <cuda_bf16.h>
#include <math.h>
#include <stdint.h>

// ---------------- problem constants ----------------
#define VV    50000
#define OOV_N 100
#define VO    50100
#define EE    128
#define HH    256
#define BB    32
#define SS    256
#define TT    16
#define BTVO  ((size_t)BB * TT * VO)   // 25,651,200
#define LOG1EM10 (-23.025850929940457f)

// vocab mma smem strides (bf16 units)
#define BSTR 136
#define ASTR 264
#define VOCAB_SMEM (256*BSTR*2 + 64*ASTR*2 + 64*4)   // 103,680 B

// ---------------- static device scratch (no runtime alloc) ----------------
__device__ float d_zx_enc[(size_t)BB * SS * 4 * HH];
__device__ float d_zx_dec[BB * TT * 4 * HH];
__device__ float d_enc_out[(size_t)BB * SS * HH];
__device__ float d_dec_out[BB * TT * HH];
__device__ float d_ehec[2 * BB * HH];      // rows 0..31 = eh, 32..63 = ec
__device__ float d_h0c0[2 * BB * HH];      // rows 0..31 = h0, 32..63 = c0
__device__ float d_encWc[(size_t)BB * SS * HH];
__device__ float d_attn[BB * TT * HH];
__device__ float d_rowsum[BB * TT];
__device__ float d_logz[BB * TT];
__device__ float d_fixval[BB * TT * SS];
__device__ float d_copyacc[BTVO];
__device__ float d_zero[BB * HH];          // stays zero forever

__device__ volatile unsigned g_bar_cnt;
__device__ volatile unsigned g_bar_gen;

// ================= grid barrier (all CTAs co-resident) =================
__device__ __forceinline__ void grid_barrier(unsigned nblocks) {
    __threadfence();
    __syncthreads();
    if (threadIdx.x == 0) {
        unsigned gen = g_bar_gen;
        unsigned arr = atomicAdd((unsigned*)&g_bar_cnt, 1u);
        if (arr == nblocks - 1u) {
            g_bar_cnt = 0u;
            __threadfence();
            g_bar_gen = gen + 1u;
        } else {
            while (g_bar_gen == gen) { }
        }
        __threadfence();
    }
    __syncthreads();
}

// ================= small SGEMM, spill-proof: 128x64 tile, 8x4 micro =================
// C = op(A @ B + bias).  A: MxK (or gathered emb rows), B: KxN, C: MxN (ldc=N).
// M % 128 == 0, N % 64 == 0, K % 16 == 0 for all call sites.
// MODE 0: none, 1: tanh.  GATHER 1: A row r = emb[tokens[r]].
template <int MODE, int GATHER>
__global__ void __launch_bounds__(256)
sgemm_small(const float* __restrict__ A, const int* __restrict__ tokens,
            const float* __restrict__ emb, const float* __restrict__ B,
            float* __restrict__ C, int M, int N, int K,
            const float* __restrict__ bias) {
    __shared__ float As[16][132];
    __shared__ float Bs[16][68];

    const int tid  = threadIdx.x;
    const int row0 = blockIdx.y * 128;
    const int col0 = blockIdx.x * 64;
    const int tr   = tid >> 4;    // 0..15 -> rows tr*8
    const int tc   = tid & 15;    // 0..15 -> cols tc*4

    float acc[8][4];
#pragma unroll
    for (int i = 0; i < 8; i++)
#pragma unroll
        for (int j = 0; j < 4; j++) acc[i][j] = 0.f;

    for (int k0 = 0; k0 < K; k0 += 16) {
        // A tile -> As[k][r] transposed; 2 float4 per thread
#pragma unroll
        for (int h = 0; h < 2; h++) {
            int i4 = tid + 256 * h;        // 0..511
            int r  = i4 >> 2;              // 0..127
            int kq = (i4 & 3) * 4;
            const float* src;
            if (GATHER) {
                int tok = tokens[row0 + r];
                src = &emb[(size_t)tok * K + k0 + kq];
            } else {
                src = &A[(size_t)(row0 + r) * K + k0 + kq];
            }
            float4 v = *reinterpret_cast<const float4*>(src);
            As[kq + 0][r] = v.x; As[kq + 1][r] = v.y;
            As[kq + 2][r] = v.z; As[kq + 3][r] = v.w;
        }
        // B tile: 1 float4 per thread
        {
            int kk = tid >> 4, n4 = (tid & 15) * 4;
            *reinterpret_cast<float4*>(&Bs[kk][n4]) =
                *reinterpret_cast<const float4*>(&B[(size_t)(k0 + kk) * N + col0 + n4]);
        }
        __syncthreads();

#pragma unroll
        for (int kk = 0; kk < 16; kk++) {
            float4 a0 = *reinterpret_cast<const float4*>(&As[kk][tr * 8]);
            float4 a1 = *reinterpret_cast<const float4*>(&As[kk][tr * 8 + 4]);
            float4 b0 = *reinterpret_cast<const float4*>(&Bs[kk][tc * 4]);
            float a[8] = {a0.x, a0.y, a0.z, a0.w, a1.x, a1.y, a1.z, a1.w};
            float b[4] = {b0.x, b0.y, b0.z, b0.w};
#pragma unroll
            for (int i = 0; i < 8; i++)
#pragma unroll
                for (int j = 0; j < 4; j++) acc[i][j] += a[i] * b[j];
        }
        __syncthreads();
    }

#pragma unroll
    for (int i = 0; i < 8; i++) {
        int r = row0 + tr * 8 + i;
#pragma unroll
        for (int j = 0; j < 4; j++) {
            int c = col0 + tc * 4 + j;
            float v = acc[i][j];
            if (bias) v += bias[c];
            if (MODE == 1) v = tanhf(v);
            C[(size_t)r * N + c] = v;
        }
    }
}

// ================= persistent LSTM (128 CTAs x 256 threads) =================
// CTA owns 2 hidden units (8 gate-outputs), 1 thread per (gate-output, batch).
// Optional prologue: h0c0[o] = be2d[col] + ehec[row]@We2d (64x256), then barrier.
__global__ void __launch_bounds__(256, 1)
lstm_kernel(const float* __restrict__ zx, const float* __restrict__ U,
            const float* __restrict__ h0, const float* __restrict__ c0,
            float* __restrict__ hist, float* __restrict__ h_fin,
            float* __restrict__ c_fin, int steps,
            int do_prol, const float* __restrict__ ehec,
            const float* __restrict__ We2d, const float* __restrict__ be2d,
            float* __restrict__ h0c0w) {
    __shared__ float hs[256 * 33];   // [k][b] padded
    __shared__ float zs[256];        // [jj*32 + b]

    const int tid  = threadIdx.x;
    const int u0   = blockIdx.x * 2;
    const int b    = tid & 31;
    const int jj   = tid >> 5;               // 0..7
    const int gate = jj >> 1, unit = jj & 1;
    const int j    = gate * 256 + u0 + unit;
    const unsigned nblk = gridDim.x;

    if (do_prol) {
        if (tid < 128) {
            int o = blockIdx.x * 128 + tid;   // 0..16383
            int row = o >> 8, col = o & 255;
            float a = be2d[col];
            const float* er = &ehec[row * 256];
#pragma unroll 4
            for (int k = 0; k < 256; k++) a += er[k] * We2d[k * 256 + col];
            h0c0w[o] = a;
        }
        grid_barrier(nblk);
    }

    // update-role cell state (threads 0..63)
    const int ub = tid & 31;
    const int un = (tid >> 5) & 1;
    float c_reg = 0.f;
    if (tid < 64) c_reg = c0[ub * 256 + u0 + un];

    for (int s = 0; s < steps; s++) {
        // stage h_prev (32x256) transposed [k][b]
        if (s == 0) {
#pragma unroll 8
            for (int it = 0; it < 32; it++)
                hs[tid * 33 + it] = h0[it * 256 + tid];
        } else {
#pragma unroll 8
            for (int it = 0; it < 32; it++)
                hs[tid * 33 + it] = hist[((size_t)it * steps + (s - 1)) * 256 + tid];
        }
        __syncthreads();

        float a0 = zx[((size_t)b * steps + s) * 1024 + j];
        float a1 = 0.f, a2 = 0.f, a3 = 0.f;
#pragma unroll 4
        for (int k = 0; k < 256; k += 4) {
            a0 += __ldg(&U[(k + 0) * 1024 + j]) * hs[(k + 0) * 33 + b];
            a1 += __ldg(&U[(k + 1) * 1024 + j]) * hs[(k + 1) * 33 + b];
            a2 += __ldg(&U[(k + 2) * 1024 + j]) * hs[(k + 2) * 33 + b];
            a3 += __ldg(&U[(k + 3) * 1024 + j]) * hs[(k + 3) * 33 + b];
        }
        zs[jj * 32 + b] = (a0 + a1) + (a2 + a3);
        __syncthreads();

        if (tid < 64) {
            float iv = zs[(0 * 2 + un) * 32 + ub];
            float fv = zs[(1 * 2 + un) * 32 + ub];
            float gv = zs[(2 * 2 + un) * 32 + ub];
            float ov = zs[(3 * 2 + un) * 32 + ub];
            float ig = 1.f / (1.f + expf(-iv));
            float fg = 1.f / (1.f + expf(-fv));
            float og = 1.f / (1.f + expf(-ov));
            c_reg = fg * c_reg + ig * tanhf(gv);
            float h = og * tanhf(c_reg);
            hist[((size_t)ub * steps + s) * 256 + u0 + un] = h;
            if (s == steps - 1) {
                h_fin[ub * 256 + u0 + un] = h;
                c_fin[ub * 256 + u0 + un] = c_reg;
            }
        }
        grid_barrier(nblk);
    }
}

// ================= fused attention (dWa + softmax + ctx + Wout) =================
__global__ void __launch_bounds__(256)
attn_mega(const float* __restrict__ dec, const float* __restrict__ enc,
          const float* __restrict__ Wattn, const float* __restrict__ Wout,
          const float* __restrict__ bout, const int* __restrict__ x_len,
          float* __restrict__ attn_out, float* __restrict__ rowsum) {
    __shared__ float dec_s[256];
    __shared__ float q_s[256];
    __shared__ float aw_s[256];
    __shared__ float red[8];

    const int bt = blockIdx.x;
    const int b  = bt >> 4;
    const int tid = threadIdx.x;

    dec_s[tid] = dec[(size_t)bt * 256 + tid];
    if (tid == 0) rowsum[bt] = 1e-8f;   // OOV pad: 100 * 1e-10
    __syncthreads();

    // q = dec @ Wattn  (thread = output dim e)
    {
        float a = 0.f;
#pragma unroll 4
        for (int k = 0; k < 256; k++) a += dec_s[k] * Wattn[k * 256 + tid];
        q_s[tid] = a;
    }
    __syncthreads();

    // scores: thread = source pos s
    const float* er = enc + ((size_t)b * SS + tid) * 256;
    float dot = 0.f;
#pragma unroll 4
    for (int k = 0; k < 256; k += 4) {
        float4 e = *reinterpret_cast<const float4*>(&er[k]);
        dot += q_s[k] * e.x + q_s[k + 1] * e.y + q_s[k + 2] * e.z + q_s[k + 3] * e.w;
    }
    const int len = x_len[b];
    float sc = (tid < len) ? dot : -1e30f;

    float m = sc;
#pragma unroll
    for (int o = 16; o; o >>= 1) m = fmaxf(m, __shfl_xor_sync(~0u, m, o));
    if ((tid & 31) == 0) red[tid >> 5] = m;
    __syncthreads();
    float mx = red[0];
#pragma unroll
    for (int w = 1; w < 8; w++) mx = fmaxf(mx, red[w]);
    __syncthreads();

    float e = (tid < len) ? __expf(sc - mx) : 0.f;
    float sm = e;
#pragma unroll
    for (int o = 16; o; o >>= 1) sm += __shfl_xor_sync(~0u, sm, o);
    if ((tid & 31) == 0) red[tid >> 5] = sm;
    __syncthreads();
    float tot = 0.f;
#pragma unroll
    for (int w = 0; w < 8; w++) tot += red[w];
    aw_s[tid] = e / tot;
    __syncthreads();

    // ctx: thread = embedding dim
    float cx = 0.f;
    const float* eb = enc + (size_t)b * SS * 256 + tid;
    for (int s = 0; s < SS; s++) cx += aw_s[s] * eb[(size_t)s * 256];
    __syncthreads();
    q_s[tid] = cx;                 // q_s now holds ctx
    __syncthreads();

    // attn_out = tanh([ctx, dec] @ Wout + bout)
    float a2 = bout[tid];
#pragma unroll 4
    for (int k = 0; k < 256; k++) a2 += q_s[k] * Wout[k * 256 + tid];
#pragma unroll 4
    for (int k = 0; k < 256; k++) a2 += dec_s[k] * Wout[(256 + k) * 256 + tid];
    attn_out[(size_t)bt * 256 + tid] = tanhf(a2);
}

// ================= vocab GEMM on tensor cores (bf16 mma) =================
__device__ __forceinline__ uint32_t smem_u32(const void* p) {
    return (uint32_t)__cvta_generic_to_shared(p);
}
__device__ __forceinline__ void ldsm_x4(uint32_t* r, uint32_t addr) {
    asm volatile("ldmatrix.sync.aligned.m8n8.x4.shared.b16 {%0,%1,%2,%3}, [%4];"
                 : "=r"(r[0]), "=r"(r[1]), "=r"(r[2]), "=r"(r[3]) : "r"(addr));
}
__device__ __forceinline__ void ldsm_x2_trans(uint32_t* r, uint32_t addr) {
    asm volatile("ldmatrix.sync.aligned.m8n8.x2.trans.shared.b16 {%0,%1}, [%2];"
                 : "=r"(r[0]), "=r"(r[1]) : "r"(addr));
}
__device__ __forceinline__ void mma_bf16(float* d, const uint32_t* a, const uint32_t* b) {
    asm volatile("mma.sync.aligned.m16n8k16.row.col.f32.bf16.bf16.f32 "
                 "{%0,%1,%2,%3}, {%4,%5,%6,%7}, {%8,%9}, {%0,%1,%2,%3};"
                 : "+f"(d[0]), "+f"(d[1]), "+f"(d[2]), "+f"(d[3])
                 : "r"(a[0]), "r"(a[1]), "r"(a[2]), "r"(a[3]), "r"(b[0]), "r"(b[1]));
}

// One CTA per 128-col strip of Wgen; loops over all M=512 rows.
// Writes raw logits to out (row stride VO) and atomically accumulates
// per-row exp-sums (via __expf) into rowsum.
__global__ void __launch_bounds__(256)
vocab_kernel(const float* __restrict__ A,      // attn_out 512x256 fp32
             const float* __restrict__ Wgen,   // 256x50000 fp32
             float* __restrict__ out, float* __restrict__ rowsum) {
    extern __shared__ char dsm[];
    __nv_bfloat16* Bsh = (__nv_bfloat16*)dsm;                        // [256][BSTR]
    __nv_bfloat16* Ash = (__nv_bfloat16*)(dsm + 256 * BSTR * 2);     // [64][ASTR]
    float* rsumsh = (float*)(dsm + 256 * BSTR * 2 + 64 * ASTR * 2);  // [64]

    const int tid  = threadIdx.x;
    const int lane = tid & 31, wid = tid >> 5;
    const int n0   = blockIdx.x * 128;
    const int wm   = wid >> 2, wn = wid & 3;     // warps 2(m) x 4(n)
    const int m_off = wm * 32, n_off = wn * 32;

    // ---- stage B strip once: 256(k) x 128(n), fp32 -> bf16 ----
    for (int i = tid; i < 256 * 32; i += 256) {
        int k  = i >> 5;
        int n4 = (i & 31) << 2;
        int gn = n0 + n4;
        float4 v;
        if (gn + 3 < VV) {
            v = *reinterpret_cast<const float4*>(&Wgen[(size_t)k * VV + gn]);
        } else {
            float t0 = (gn + 0 < VV) ? Wgen[(size_t)k * VV + gn + 0] : 0.f;
            float t1 = (gn + 1 < VV) ? Wgen[(size_t)k * VV + gn + 1] : 0.f;
            float t2 = (gn + 2 < VV) ? Wgen[(size_t)k * VV + gn + 2] : 0.f;
            float t3 = (gn + 3 < VV) ? Wgen[(size_t)k * VV + gn + 3] : 0.f;
            v = make_float4(t0, t1, t2, t3);
        }
        __nv_bfloat162* dst = reinterpret_cast<__nv_bfloat162*>(&Bsh[k * BSTR + n4]);
        dst[0] = __floats2bfloat162_rn(v.x, v.y);
        dst[1] = __floats2bfloat162_rn(v.z, v.w);
    }
    if (tid < 64) rsumsh[tid] = 0.f;
    __syncthreads();

    for (int mb = 0; mb < 8; mb++) {
        const int m0 = mb * 64;
        // ---- stage A block: 64(m) x 256(k) ----
        for (int i = tid; i < 64 * 64; i += 256) {
            int r  = i >> 6;
            int k4 = (i & 63) << 2;
            float4 v = *reinterpret_cast<const float4*>(&A[(size_t)(m0 + r) * 256 + k4]);
            __nv_bfloat162* dst = reinterpret_cast<__nv_bfloat162*>(&Ash[r * ASTR + k4]);
            dst[0] = __floats2bfloat162_rn(v.x, v.y);
            dst[1] = __floats2bfloat162_rn(v.z, v.w);
        }
        __syncthreads();

        float acc[2][4][4];
#pragma unroll
        for (int mf = 0; mf < 2; mf++)
#pragma unroll
            for (int nf = 0; nf < 4; nf++)
#pragma unroll
                for (int q = 0; q < 4; q++) acc[mf][nf][q] = 0.f;

#pragma unroll
        for (int ks = 0; ks < 16; ks++) {
            const int k0 = ks * 16;
            uint32_t afr[2][4];
#pragma unroll
            for (int mf = 0; mf < 2; mf++) {
                const __nv_bfloat16* ap =
                    &Ash[(m_off + mf * 16 + (lane & 15)) * ASTR + k0 + (lane >> 4) * 8];
                ldsm_x4(afr[mf], smem_u32(ap));
            }
            uint32_t bfr[4][2];
#pragma unroll
            for (int nf = 0; nf < 4; nf++) {
                const __nv_bfloat16* bp =
                    &Bsh[(k0 + (lane & 15)) * BSTR + n_off + nf * 8];
                ldsm_x2_trans(bfr[nf], smem_u32(bp));
            }
#pragma unroll
            for (int mf = 0; mf < 2; mf++)
#pragma unroll
                for (int nf = 0; nf < 4; nf++)
                    mma_bf16(acc[mf][nf], afr[mf], bfr[nf]);
        }

        // ---- epilogue: store logits + __expf row partial sums ----
        float psum[4] = {0.f, 0.f, 0.f, 0.f};
#pragma unroll
        for (int mf = 0; mf < 2; mf++) {
            int gr0 = m0 + m_off + mf * 16 + (lane >> 2);
#pragma unroll
            for (int nf = 0; nf < 4; nf++) {
                int gc = n0 + n_off + nf * 8 + (lane & 3) * 2;
                float v0 = acc[mf][nf][0], v1 = acc[mf][nf][1];
                float v2 = acc[mf][nf][2], v3 = acc[mf][nf][3];
                if (gc + 1 < VV) {
                    *reinterpret_cast<float2*>(&out[(size_t)gr0 * VO + gc]) = make_float2(v0, v1);
                    *reinterpret_cast<float2*>(&out[(size_t)(gr0 + 8) * VO + gc]) = make_float2(v2, v3);
                    psum[mf * 2 + 0] += __expf(v0) + __expf(v1);
                    psum[mf * 2 + 1] += __expf(v2) + __expf(v3);
                } else if (gc < VV) {
                    out[(size_t)gr0 * VO + gc] = v0;
                    out[(size_t)(gr0 + 8) * VO + gc] = v2;
                    psum[mf * 2 + 0] += __expf(v0);
                    psum[mf * 2 + 1] += __expf(v2);
                }
            }
        }
        {
            int lr = m_off + (lane >> 2);
            atomicAdd(&rsumsh[lr + 0],  psum[0]);
            atomicAdd(&rsumsh[lr + 8],  psum[1]);
            atomicAdd(&rsumsh[lr + 16], psum[2]);
            atomicAdd(&rsumsh[lr + 24], psum[3]);
        }
        __syncthreads();
        if (tid < 64) {
            atomicAdd(&rowsum[m0 + tid], rsumsh[tid]);
            rsumsh[tid] = 0.f;
        }
        __syncthreads();
    }
}

// ================= encWc zero targets =================
__global__ void copyzero_kernel(float* __restrict__ copyacc, const int* __restrict__ xov,
                                const int* __restrict__ x_len) {
    const int bt = blockIdx.x;
    const int b  = bt >> 4;
    const int s  = threadIdx.x;
    if (s < x_len[b]) copyacc[(size_t)bt * VO + xov[b * SS + s]] = 0.f;
}

// ================= copy scores + scatter =================
__global__ void __launch_bounds__(256)
copy_scatter_kernel(const float* __restrict__ encWc, const float* __restrict__ attn,
                    const int* __restrict__ xov, const int* __restrict__ x_len,
                    float* __restrict__ copyacc, float* __restrict__ rowsum) {
    __shared__ float a[256];
    const int bt = blockIdx.x;
    const int b  = bt >> 4;
    const int tid = threadIdx.x;

    a[tid] = attn[(size_t)bt * 256 + tid];
    __syncthreads();

    if (tid < x_len[b]) {
        const float* r = encWc + ((size_t)b * SS + tid) * 256;
        float dot = 0.f;
#pragma unroll 4
        for (int k = 0; k < 256; k += 4) {
            float4 e = *reinterpret_cast<const float4*>(&r[k]);
            dot += a[k] * e.x + a[k + 1] * e.y + a[k + 2] * e.z + a[k + 3] * e.w;
        }
        float v = expf(dot);
        atomicAdd(&copyacc[(size_t)bt * VO + xov[b * SS + tid]], v);
        atomicAdd(&rowsum[bt], v);
    }
}

// ================= fixval = log(exp(logit) + copy) for touched entries =================
__global__ void fixval_kernel(const float* __restrict__ out, const float* __restrict__ copyacc,
                              const int* __restrict__ xov, const int* __restrict__ x_len,
                              float* __restrict__ fixval) {
    const int bt = blockIdx.x;
    const int b  = bt >> 4;
    const int s  = threadIdx.x;
    if (s < x_len[b]) {
        int idx = xov[b * SS + s];
        float base = (idx < VV) ? expf(out[(size_t)bt * VO + idx]) : 1e-10f;
        fixval[bt * SS + s] = logf(base + copyacc[(size_t)bt * VO + idx]);
    }
}

__global__ void logz_kernel(const float* __restrict__ rs, float* __restrict__ lz) {
    int i = threadIdx.x + blockIdx.x * blockDim.x;
    if (i < BB * TT) lz[i] = logf(rs[i]);
}

__global__ void finalize_kernel(float* __restrict__ out, const float* __restrict__ lz) {
    const int row = blockIdx.y;
    const int c4  = (blockIdx.x * 256 + threadIdx.x) * 4;
    if (c4 >= VO) return;
    float z = lz[row];
    float* p = out + (size_t)row * VO + c4;
    if (c4 + 3 < VV) {
        float4 v = *reinterpret_cast<float4*>(p);
        v.x -= z; v.y -= z; v.z -= z; v.w -= z;
        *reinterpret_cast<float4*>(p) = v;
    } else {
#pragma unroll
        for (int j = 0; j < 4; j++) {
            int c = c4 + j;
            if (c < VO) p[j] = (c < VV) ? p[j] - z : LOG1EM10 - z;
        }
    }
}

__global__ void fixwrite_kernel(float* __restrict__ out, const float* __restrict__ fixval,
                                const float* __restrict__ lz, const int* __restrict__ xov,
                                const int* __restrict__ x_len) {
    const int bt = blockIdx.x;
    const int b  = bt >> 4;
    const int s  = threadIdx.x;
    if (s < x_len[b]) {
        int idx = xov[b * SS + s];
        out[(size_t)bt * VO + idx] = fixval[bt * SS + s] - lz[bt];
    }
}

// ================= host side =================
extern "C" void kernel_launch(void* const* d_in, const int* in_sizes, int n_in,
                              void* d_out, int out_size) {
    const int*   x     = (const int*)d_in[0];
    const int*   xov   = (const int*)d_in[1];
    const int*   xlen  = (const int*)d_in[2];
    const int*   dx    = (const int*)d_in[3];
    const float* emb   = (const float*)d_in[4];
    const float* Wenc  = (const float*)d_in[5];
    const float* Uenc  = (const float*)d_in[6];
    const float* benc  = (const float*)d_in[7];
    const float* We2d  = (const float*)d_in[8];
    const float* be2d  = (const float*)d_in[9];
    const float* Wdec  = (const float*)d_in[10];
    const float* Udec  = (const float*)d_in[11];
    const float* bdec  = (const float*)d_in[12];
    const float* Wattn = (const float*)d_in[13];
    const float* Wout  = (const float*)d_in[14];
    const float* bout  = (const float*)d_in[15];
    const float* Wgen  = (const float*)d_in[16];
    const float* Wcopy = (const float*)d_in[17];
    const float* bcopy = (const float*)d_in[18];
    float* out = (float*)d_out;
    (void)in_sizes; (void)n_in; (void)out_size;

    void* p;
    cudaGetSymbolAddress(&p, d_zx_enc);  float* s_zx_enc  = (float*)p;
    cudaGetSymbolAddress(&p, d_zx_dec);  float* s_zx_dec  = (float*)p;
    cudaGetSymbolAddress(&p, d_enc_out); float* s_enc_out = (float*)p;
    cudaGetSymbolAddress(&p, d_dec_out); float* s_dec_out = (float*)p;
    cudaGetSymbolAddress(&p, d_ehec);    float* s_ehec    = (float*)p;
    cudaGetSymbolAddress(&p, d_h0c0);    float* s_h0c0    = (float*)p;
    cudaGetSymbolAddress(&p, d_encWc);   float* s_encWc   = (float*)p;
    cudaGetSymbolAddress(&p, d_attn);    float* s_attn    = (float*)p;
    cudaGetSymbolAddress(&p, d_rowsum);  float* s_rowsum  = (float*)p;
    cudaGetSymbolAddress(&p, d_logz);    float* s_logz    = (float*)p;
    cudaGetSymbolAddress(&p, d_fixval);  float* s_fixval  = (float*)p;
    cudaGetSymbolAddress(&p, d_copyacc); float* s_copyacc = (float*)p;
    cudaGetSymbolAddress(&p, d_zero);    float* s_zero    = (float*)p;

    cudaFuncSetAttribute(vocab_kernel,
                         cudaFuncAttributeMaxDynamicSharedMemorySize, VOCAB_SMEM + 256);

    // 1. zx_enc = emb[x] @ Wenc + benc   (embedding gather fused)
    {
        dim3 g(1024 / 64, (BB * SS) / 128);
        sgemm_small<0, 1><<<g, 256>>>(nullptr, x, emb, Wenc, s_zx_enc,
                                      BB * SS, 4 * HH, EE, benc);
    }
    // 2. zx_dec = emb[dec_x] @ Wdec + bdec
    {
        dim3 g(1024 / 64, (BB * TT) / 128);
        sgemm_small<0, 1><<<g, 256>>>(nullptr, dx, emb, Wdec, s_zx_dec,
                                      BB * TT, 4 * HH, EE, bdec);
    }
    // 3. encoder LSTM
    lstm_kernel<<<128, 256>>>(s_zx_enc, Uenc, s_zero, s_zero,
                              s_enc_out, s_ehec, s_ehec + BB * HH, SS,
                              0, nullptr, nullptr, nullptr, nullptr);
    // 4. decoder LSTM (h0c0 GEMM fused in prologue); final h,c -> output tail
    lstm_kernel<<<128, 256>>>(s_zx_dec, Udec, s_h0c0, s_h0c0 + BB * HH,
                              s_dec_out, out + BTVO, out + BTVO + BB * HH, TT,
                              1, s_ehec, We2d, be2d, s_h0c0);
    // 5. fused attention (also inits rowsum = 1e-8)
    attn_mega<<<BB * TT, 256>>>(s_dec_out, s_enc_out, Wattn, Wout, bout, xlen,
                                s_attn, s_rowsum);
    // 6. vocab GEMM (tensor cores): logits -> out, exp-rowsums -> rowsum   [PROFILED]
    vocab_kernel<<<(VV + 127) / 128, 256, VOCAB_SMEM>>>(s_attn, Wgen, out, s_rowsum);
    // 7. encWc = tanh(enc_out @ Wcopy + bcopy)
    {
        dim3 g(256 / 64, (BB * SS) / 128);
        sgemm_small<1, 0><<<g, 256>>>(s_enc_out, nullptr, nullptr, Wcopy, s_encWc,
                                      BB * SS, HH, HH, bcopy);
    }
    // 8-9. zero scatter targets, scatter copy scores
    copyzero_kernel<<<BB * TT, 256>>>(s_copyacc, xov, xlen);
    copy_scatter_kernel<<<BB * TT, 256>>>(s_encWc, s_attn, xov, xlen, s_copyacc, s_rowsum);
    // 10. fixval (reads raw logits before finalize)
    fixval_kernel<<<BB * TT, 256>>>(out, s_copyacc, xov, xlen, s_fixval);
    // 11. logZ
    logz_kernel<<<2, 256>>>(s_rowsum, s_logz);
    // 12. normalize whole tensor
    {
        dim3 g((VO + 1023) / 1024, BB * TT);
        finalize_kernel<<<g, 256>>>(out, s_logz);
    }
    // 13. overwrite touched entries
    fixwrite_kernel<<<BB * TT, 256>>>(out, s_fixval, s_logz, xov, xlen);
}